// round 4
// baseline (speedup 1.0000x reference)
#include <cuda_runtime.h>
#include <cstdint>

// Batched outer product: out[i, j*K + l] = x[i,j] * y[i,l]
// n=4096, m=256, k=256. Pure store-bandwidth kernel (~1.07 GB written).
// At the LTS store ceiling; this round: write-back stores, 2 rows/CTA,
// shfl-broadcast x (no smem), float4 stores.

static constexpr int M = 256;
static constexpr int K = 256;
static constexpr int ROWS_PER_CTA = 2;

__global__ __launch_bounds__(256, 8)
void omul_kernel(const float* __restrict__ x,
                 const float* __restrict__ y,
                 float4* __restrict__ out)
{
    const int t    = threadIdx.x;
    const int w    = t >> 5;     // warp id 0..7
    const int lane = t & 31;

    #pragma unroll
    for (int r = 0; r < ROWS_PER_CTA; r++) {
        const int row = blockIdx.x * ROWS_PER_CTA + r;

        // y float4 chunk for this thread is fixed: (idx & 63) == (t & 63).
        const float4 yv =
            reinterpret_cast<const float4*>(y + (size_t)row * K)[t & 63];

        // Lane l holds x[row, l*8 + w]. Iteration i needs x[row, i*8 + w]
        // within warp w of a 2048-elem (=8 j-steps of 256) slab... mapping:
        // idx = i*256 + t; j = idx >> 6 = i*4 + (t>>6). Each warp spans
        // j = i*4 + {0..3}? No: t>>6 constant per half... use direct mapping:
        // For warp w, iteration i: j = (i*256 + w*32 + lane) >> 6
        //                            = i*4 + (w >> 1)      (lane-independent)
        // So x index depends only on i and w: j = i*4 + (w>>1).
        // Preload per-lane x[ lane*4 + (w>>1) ]... lane*4 covers i via shfl:
        // broadcast lane i gives j = i*4 + (w>>1). Need i in 0..63 but only
        // 32 lanes -> split into two halves with two preloaded registers.
        const int jbase = (w >> 1);
        const float xr0 = x[(size_t)row * M + (lane * 4 + jbase)];
        const float xr1 = x[(size_t)row * M + ((lane + 32) * 4 + jbase)];

        float4* o = out + (size_t)row * ((M * K) / 4);

        #pragma unroll 8
        for (int i = 0; i < 64; i++) {
            const float xv = (i < 32) ? __shfl_sync(0xFFFFFFFFu, xr0, i)
                                      : __shfl_sync(0xFFFFFFFFu, xr1, i - 32);
            float4 rr;
            rr.x = xv * yv.x;
            rr.y = xv * yv.y;
            rr.z = xv * yv.z;
            rr.w = xv * yv.w;
            o[i * 256 + t] = rr;   // default write-back caching
        }
    }
}

extern "C" void kernel_launch(void* const* d_in, const int* in_sizes, int n_in,
                              void* d_out, int out_size)
{
    const float* x = (const float*)d_in[0];
    const float* y = (const float*)d_in[1];
    float4* out = (float4*)d_out;

    const int n = in_sizes[0] / M;           // 4096 rows
    omul_kernel<<<n / ROWS_PER_CTA, 256>>>(x, y, out);
}

// round 6
// speedup vs baseline: 1.0837x; 1.0837x over previous
#include <cuda_runtime.h>
#include <cstdint>

// Batched outer product: out[i, j*K + l] = x[i,j] * y[i,l]
// n=4096, m=256, k=256 → out row = 65536 f32 = 16384 float4.
// Pure store-bandwidth kernel (~1.07 GB written) at the HBM write wall.
// Best-measured config: smem-staged x, float4 .cs streaming stores,
// 1 row per CTA, grid=4096, full unroll.

static constexpr int M = 256;   // x row length
static constexpr int K = 256;   // y row length
static constexpr int ROW_F4 = (M * K) / 4;  // 16384 float4 per output row

__global__ __launch_bounds__(256, 8)
void omul_kernel(const float* __restrict__ x,
                 const float* __restrict__ y,
                 float4* __restrict__ out)
{
    __shared__ float xs[M];

    const int row = blockIdx.x;
    const int t   = threadIdx.x;

    // Stage x row in smem (conflict-free broadcast reads later);
    // y float4 chunk is fixed per thread: (idx & 63) == (t & 63).
    xs[t] = x[(size_t)row * M + t];
    const float4 yv = reinterpret_cast<const float4*>(y + (size_t)row * K)[t & 63];
    __syncthreads();

    float4* o = out + (size_t)row * ROW_F4;

    // 64 iterations × 256 threads = 16384 float4 stores, fully coalesced,
    // ascending addresses per warp. Full unroll → ptxas batches store issue.
    #pragma unroll
    for (int i = 0; i < 64; i++) {
        const int idx = i * 256 + t;
        const float xv = xs[idx >> 6];        // warp-half broadcast, no conflicts
        float4 r;
        r.x = xv * yv.x;
        r.y = xv * yv.y;
        r.z = xv * yv.z;
        r.w = xv * yv.w;
        __stcs(&o[idx], r);                   // evict-first streaming store
    }
}

extern "C" void kernel_launch(void* const* d_in, const int* in_sizes, int n_in,
                              void* d_out, int out_size)
{
    const float* x = (const float*)d_in[0];
    const float* y = (const float*)d_in[1];
    float4* out = (float4*)d_out;

    const int n = in_sizes[0] / M;  // 4096 rows
    omul_kernel<<<n, 256>>>(x, y, out);
}